// round 8
// baseline (speedup 1.0000x reference)
#include <cuda_runtime.h>
#include <math.h>
#include <stdint.h>

#define BN_EPS 1e-5f
#define SPB 8                  /* samples per tile = warps per block */
#define NT 256
#define DEPTH 3
#define BPSM 3
#define NSM 148
#define GRID (NSM * BPSM)      /* 444 blocks, guaranteed co-resident */
#define MAXB 65536
#define TILE_FLOATS (SPB * 576)             /* 4608 */
#define TILE_BYTES  (TILE_FLOATS * 4)       /* 18432 */

// persistent scratch (no allocation allowed)
__device__ float g_zbuf[MAXB * 4];
__device__ float g_part[GRID * 8];
__device__ unsigned g_bar;     // monotone arrival counter (never reset)

__device__ __forceinline__ uint32_t smem_u32(const void* p) {
    uint32_t a;
    asm("{ .reg .u64 t; cvta.to.shared.u64 t, %1; cvt.u32.u64 %0, t; }"
        : "=r"(a) : "l"(p));
    return a;
}
__device__ __forceinline__ void mbar_init(uint32_t m, uint32_t cnt) {
    asm volatile("mbarrier.init.shared.b64 [%0], %1;" :: "r"(m), "r"(cnt) : "memory");
}
__device__ __forceinline__ void mbar_expect_tx(uint32_t m, uint32_t bytes) {
    asm volatile("mbarrier.arrive.expect_tx.shared.b64 _, [%0], %1;"
                 :: "r"(m), "r"(bytes) : "memory");
}
__device__ __forceinline__ void bulk_ld(uint32_t dst, const void* src,
                                        uint32_t bytes, uint32_t m) {
    asm volatile("cp.async.bulk.shared::cluster.global.mbarrier::complete_tx::bytes "
                 "[%0], [%1], %2, [%3];"
                 :: "r"(dst), "l"(src), "r"(bytes), "r"(m) : "memory");
}
__device__ __forceinline__ void mbar_wait(uint32_t m, uint32_t phase) {
    uint32_t done;
    asm volatile("{\n\t.reg .pred p;\n\t"
                 "mbarrier.try_wait.parity.acquire.cta.shared::cta.b64 p, [%1], %2;\n\t"
                 "selp.b32 %0, 1, 0, p;\n\t}"
                 : "=r"(done) : "r"(m), "r"(phase) : "memory");
    if (!done) {
        asm volatile("{\n\t.reg .pred P1;\n\t"
                     "W_%=:\n\t"
                     "mbarrier.try_wait.parity.acquire.cta.shared::cta.b64 P1, [%0], %1, 0x989680;\n\t"
                     "@P1 bra.uni D_%=;\n\t"
                     "bra.uni W_%=;\n\t"
                     "D_%=:\n\t}" :: "r"(m), "r"(phase) : "memory");
    }
}

__global__ void __launch_bounds__(NT, BPSM) k_fused(
        const float* __restrict__ x,
        const float* __restrict__ enc_w,
        const float* __restrict__ enc_b,
        const float* __restrict__ vp,
        const float* __restrict__ gamma,
        const float* __restrict__ beta,
        float* __restrict__ out,
        int B, int ntiles)
{
    __shared__ __align__(128) float buf[DEPTH][TILE_FLOATS];  // 55296 B
    __shared__ __align__(8) uint64_t mbar[DEPTH];
    __shared__ float Us[2 * 256];     // U re|im (init only)
    __shared__ float pw[SPB][28];     // per-warp: pooled[16] + cs[8] + pad
    __shared__ float encs[68];        // enc_w(64) + enc_b(4)
    __shared__ float wacc[SPB][8];    // per-warp BN partials
    __shared__ float stat[8];

    const int tid = threadIdx.x;
    const int wid = tid >> 5;
    const int lid = tid & 31;

    uint32_t mbs[DEPTH], sbs[DEPTH];
#pragma unroll
    for (int d = 0; d < DEPTH; d++) {
        mbs[d] = smem_u32(&mbar[d]);
        sbs[d] = smem_u32(&buf[d][0]);
    }

    // ---- stage encoder ----
    if (tid >= 32 && tid < 96)  encs[tid - 32] = enc_w[tid - 32];
    if (tid >= 96 && tid < 100) encs[64 + tid - 96] = enc_b[tid - 96];

    // ---- mbarrier init + pipeline prologue (3 stages) ----
    if (tid == 0) {
#pragma unroll
        for (int d = 0; d < DEPTH; d++) mbar_init(mbs[d], 1);
        asm volatile("fence.proxy.async.shared::cta;" ::: "memory");
#pragma unroll
        for (int d = 0; d < DEPTH; d++) {
            int t = blockIdx.x + d * GRID;
            if (t < ntiles) {
                int ns = min(SPB, B - t * SPB);
                mbar_expect_tx(mbs[d], ns * 2304u);
                bulk_ld(sbs[d], x + (long)t * TILE_FLOATS, ns * 2304u, mbs[d]);
            }
        }
    }

    // ---- warp 0: build fixed variational unitary U into smem ----
    if (tid < 16) {
        float re[16], im[16];
#pragma unroll
        for (int b = 0; b < 16; b++) { re[b] = (b == tid) ? 1.f : 0.f; im[b] = 0.f; }
#pragma unroll
        for (int d = 0; d < 2; d++) {
#pragma unroll
            for (int w = 0; w < 4; w++) {
                const int mask = 8 >> w;
                float cx, sx, cy, sy, cz, sz;
                sincosf(0.5f * vp[d * 12 + w * 3 + 0], &sx, &cx);
                sincosf(0.5f * vp[d * 12 + w * 3 + 1], &sy, &cy);
                sincosf(0.5f * vp[d * 12 + w * 3 + 2], &sz, &cz);
#pragma unroll
                for (int b = 0; b < 16; b++) {
                    if (b & mask) continue;
                    const int b1 = b | mask;
                    float r0, i0, r1, i1;
                    r0 = re[b]; i0 = im[b]; r1 = re[b1]; i1 = im[b1];
                    re[b]  = cx * r0 + sx * i1;  im[b]  = cx * i0 - sx * r1;
                    re[b1] = cx * r1 + sx * i0;  im[b1] = cx * i1 - sx * r0;
                    r0 = re[b]; i0 = im[b]; r1 = re[b1]; i1 = im[b1];
                    re[b]  = cy * r0 - sy * r1;  im[b]  = cy * i0 - sy * i1;
                    re[b1] = sy * r0 + cy * r1;  im[b1] = sy * i0 + cy * i1;
                    r0 = re[b]; i0 = im[b]; r1 = re[b1]; i1 = im[b1];
                    re[b]  = cz * r0 + sz * i0;  im[b]  = cz * i0 - sz * r0;
                    re[b1] = cz * r1 - sz * i1;  im[b1] = cz * i1 + sz * r1;
                }
            }
#pragma unroll
            for (int c = 0; c < 4; c++) {
                const int tg = (c + 1) & 3;
                const int mc = 8 >> c, mt = 8 >> tg;
#pragma unroll
                for (int b = 0; b < 16; b++) {
                    if ((b & mc) && !(b & mt)) {
                        const int b1 = b | mt;
                        float tr = re[b], ti = im[b];
                        re[b] = re[b1]; im[b] = im[b1];
                        re[b1] = tr;    im[b1] = ti;
                    }
                }
            }
        }
#pragma unroll
        for (int b = 0; b < 16; b++) {
            Us[b * 16 + tid]       = re[b];
            Us[256 + b * 16 + tid] = im[b];
        }
    }
    __syncthreads();

    // ---- my U row into registers, sign-folded by (-i)^popc(col) ----
    const int cj = lid & 15;
    float fr[16], fi[16];
#pragma unroll
    for (int t = 0; t < 16; t++) {
        float urv = Us[cj * 16 + t], uiv = Us[256 + cj * 16 + t];
        const int k4 = __popc(t) & 3;
        if (k4 == 0)      { fr[t] = urv;  fi[t] = uiv;  }
        else if (k4 == 1) { fr[t] = uiv;  fi[t] = -urv; }
        else if (k4 == 2) { fr[t] = -urv; fi[t] = -uiv; }
        else              { fr[t] = -uiv; fi[t] = urv;  }
    }

    float accS0 = 0.f, accS1 = 0.f, accS2 = 0.f, accS3 = 0.f;
    float accQ0 = 0.f, accQ1 = 0.f, accQ2 = 0.f, accQ3 = 0.f;

    // ============ persistent tile loop: 1 warp = 1 sample ============
    int it = 0;
    for (int tile = blockIdx.x; tile < ntiles; tile += GRID, it++) {
        int stage = it % DEPTH;
        const uint32_t mb = mbs[stage];
        const int samp0 = tile * SPB;
        const int nsamp = min(SPB, B - samp0);
        const bool live = (wid < nsamp);

        mbar_wait(mb, (it / DEPTH) & 1);

        // ---- warp-local pooling: lanes 0..23 each pool one image row ----
        float h0 = 0.f, h1 = 0.f, h2 = 0.f, h3 = 0.f;
        if (live && lid < 24) {
            const float4* rp = (const float4*)(&buf[stage][0]) + wid * 144 + lid * 6;
            float4 a = rp[0], b = rp[1], c = rp[2], d = rp[3], e = rp[4], f = rp[5];
            h0 = a.x + a.y + a.z + a.w + b.x + b.y;
            h1 = b.z + b.w + c.x + c.y + c.z + c.w;
            h2 = d.x + d.y + d.z + d.w + e.x + e.y;
            h3 = e.z + e.w + f.x + f.y + f.z + f.w;
        }
        // vertical 6-row sum: p2 = 2-row, p4 = 4-row, p6 = p4 + p2(lane+4)
        {
            float p2, p4;
            p2 = h0 + __shfl_down_sync(0xffffffffu, h0, 1);
            p4 = p2 + __shfl_down_sync(0xffffffffu, p2, 2);
            h0 = p4 + __shfl_down_sync(0xffffffffu, p2, 4);
            p2 = h1 + __shfl_down_sync(0xffffffffu, h1, 1);
            p4 = p2 + __shfl_down_sync(0xffffffffu, p2, 2);
            h1 = p4 + __shfl_down_sync(0xffffffffu, p2, 4);
            p2 = h2 + __shfl_down_sync(0xffffffffu, h2, 1);
            p4 = p2 + __shfl_down_sync(0xffffffffu, p2, 2);
            h2 = p4 + __shfl_down_sync(0xffffffffu, p2, 4);
            p2 = h3 + __shfl_down_sync(0xffffffffu, h3, 1);
            p4 = p2 + __shfl_down_sync(0xffffffffu, p2, 2);
            h3 = p4 + __shfl_down_sync(0xffffffffu, p2, 4);
        }
        // lanes 0,6,12,18 hold the 6-row window sums for wy = lane/6
        if (live && lid < 24 && (lid % 6) == 0) {
            float* d = &pw[wid][(lid / 6) * 4];
            d[0] = h0 * (1.f / 36.f);
            d[1] = h1 * (1.f / 36.f);
            d[2] = h2 * (1.f / 36.f);
            d[3] = h3 * (1.f / 36.f);
        }
        __syncwarp();

        // ---- angles + sincos: lanes 0..3 ----
        if (live && lid < 4) {
            float a = encs[64 + lid];
#pragma unroll
            for (int kk = 0; kk < 16; kk++)
                a = fmaf(encs[lid * 16 + kk], pw[wid][kk], a);
            float sv, cv;
            __sincosf(0.5f * a, &sv, &cv);
            pw[wid][16 + lid] = cv;
            pw[wid][20 + lid] = sv;
        }
        __syncwarp();

        // ---- circuit: U row in registers ----
        float z0 = 0.f, z1 = 0.f, z2 = 0.f, z3 = 0.f;
        if (live) {
            float c0 = pw[wid][16], c1 = pw[wid][17], c2 = pw[wid][18], c3 = pw[wid][19];
            float s0 = pw[wid][20], s1 = pw[wid][21], s2 = pw[wid][22], s3 = pw[wid][23];
            float p01[4], p23[4];
            p01[0] = c0 * c1; p01[1] = c0 * s1; p01[2] = s0 * c1; p01[3] = s0 * s1;
            p23[0] = c2 * c3; p23[1] = c2 * s3; p23[2] = s2 * c3; p23[3] = s2 * s3;
            float ar = 0.f, ai = 0.f;
#pragma unroll
            for (int t = 0; t < 16; t++) {
                float v = p01[t >> 2] * p23[t & 3];
                ar = fmaf(fr[t], v, ar);
                ai = fmaf(fi[t], v, ai);
            }
            float p = ar * ar + ai * ai;
            z0 = (cj & 8) ? -p : p;
            z1 = (cj & 4) ? -p : p;
            z2 = (cj & 2) ? -p : p;
            z3 = (cj & 1) ? -p : p;
        }
#pragma unroll
        for (int off = 8; off >= 1; off >>= 1) {
            z0 += __shfl_down_sync(0xffffffffu, z0, off, 16);
            z1 += __shfl_down_sync(0xffffffffu, z1, off, 16);
            z2 += __shfl_down_sync(0xffffffffu, z2, off, 16);
            z3 += __shfl_down_sync(0xffffffffu, z3, off, 16);
        }
        if (live && lid == 0) {
            ((float4*)g_zbuf)[samp0 + wid] = make_float4(z0, z1, z2, z3);
            accS0 += z0; accS1 += z1; accS2 += z2; accS3 += z3;
            accQ0 += z0 * z0; accQ1 += z1 * z1; accQ2 += z2 * z2; accQ3 += z3 * z3;
        }

        // ---- all warps done with this buffer -> refill for tile+DEPTH*GRID ----
        __syncthreads();
        if (tid == 0) {
            const int tn = tile + DEPTH * GRID;
            if (tn < ntiles) {
                int ns = min(SPB, B - tn * SPB);
                mbar_expect_tx(mb, ns * 2304u);
                bulk_ld(sbs[stage], x + (long)tn * TILE_FLOATS, ns * 2304u, mb);
            }
        }
    }

    // ---- gather per-warp BN partials (deterministic) ----
    if (lid == 0) {
        wacc[wid][0] = accS0; wacc[wid][1] = accS1;
        wacc[wid][2] = accS2; wacc[wid][3] = accS3;
        wacc[wid][4] = accQ0; wacc[wid][5] = accQ1;
        wacc[wid][6] = accQ2; wacc[wid][7] = accQ3;
    }
    __syncthreads();
    if (tid < 4) {
        float S = 0.f, Q = 0.f;
#pragma unroll
        for (int w = 0; w < SPB; w++) {
            S += wacc[w][tid];
            Q += wacc[w][4 + tid];
        }
        g_part[blockIdx.x * 8 + tid]     = S;
        g_part[blockIdx.x * 8 + 4 + tid] = Q;
    }
    __threadfence();
    __syncthreads();
    if (tid == 0) {
        unsigned arr = atomicAdd(&g_bar, 1u) + 1u;
        unsigned target = ((arr + GRID - 1u) / GRID) * GRID;  // this launch's release
        while (*((volatile unsigned*)&g_bar) < target) {}
        __threadfence();
    }
    __syncthreads();

    // ---- redundant-but-deterministic stats reduction (each block) ----
    {
        float* red = &buf[0][0];   // reuse smem
        const int w = tid & 7, rr = tid >> 3;
        float S = 0.f;
        for (int i = rr; i < GRID; i += 32) S += g_part[i * 8 + w];
        red[tid] = S;
        __syncthreads();
#pragma unroll
        for (int step = 128; step >= 8; step >>= 1) {
            if (tid < step) red[tid] += red[tid + step];
            __syncthreads();
        }
        if (tid < 4) {
            float mean = red[tid] / (float)B;
            float var  = red[4 + tid] / (float)B - mean * mean;
            float sc   = gamma[tid] * rsqrtf(var + BN_EPS);
            stat[tid]     = sc;
            stat[4 + tid] = beta[tid] - mean * sc;
        }
        __syncthreads();
    }

    // ---- normalize (z is L2-resident) ----
    const float n0 = stat[0], n1 = stat[1], n2 = stat[2], n3 = stat[3];
    const float h0 = stat[4], h1 = stat[5], h2 = stat[6], h3 = stat[7];
    for (int b = blockIdx.x * NT + tid; b < B; b += GRID * NT) {
        float4 z = ((const float4*)g_zbuf)[b];
        ((float4*)out)[b] = make_float4(fmaf(z.x, n0, h0), fmaf(z.y, n1, h1),
                                        fmaf(z.z, n2, h2), fmaf(z.w, n3, h3));
    }
}

extern "C" void kernel_launch(void* const* d_in, const int* in_sizes, int n_in,
                              void* d_out, int out_size)
{
    const float* x      = (const float*)d_in[0];
    const float* enc_w  = (const float*)d_in[1];
    const float* enc_b  = (const float*)d_in[2];
    const float* vp     = (const float*)d_in[3];
    const float* gamma  = (const float*)d_in[4];
    const float* beta   = (const float*)d_in[5];

    const int B      = in_sizes[0] / 576;   // [B,1,24,24]
    const int ntiles = (B + SPB - 1) / SPB;

    k_fused<<<GRID, NT>>>(x, enc_w, enc_b, vp, gamma, beta,
                          (float*)d_out, B, ntiles);
}

// round 9
// speedup vs baseline: 1.2945x; 1.2945x over previous
#include <cuda_runtime.h>
#include <math.h>
#include <stdint.h>

#define BN_EPS 1e-5f
#define WPB 8                  /* warps per block */
#define NT 256
#define DEPTH 3
#define BPSM 3
#define NSM 148
#define GRID (NSM * BPSM)      /* 444 blocks, guaranteed co-resident */
#define TW (GRID * WPB)        /* 3552 total warps = sample stride */
#define MAXB 65536

// persistent scratch (no allocation allowed)
__device__ float g_zbuf[MAXB * 4];
__device__ float g_part[GRID * 8];
__device__ unsigned g_bar;     // monotone arrival counter (never reset)

__device__ __forceinline__ uint32_t smem_u32(const void* p) {
    uint32_t a;
    asm("{ .reg .u64 t; cvta.to.shared.u64 t, %1; cvt.u32.u64 %0, t; }"
        : "=r"(a) : "l"(p));
    return a;
}
__device__ __forceinline__ void mbar_init(uint32_t m, uint32_t cnt) {
    asm volatile("mbarrier.init.shared.b64 [%0], %1;" :: "r"(m), "r"(cnt) : "memory");
}
__device__ __forceinline__ void mbar_expect_tx(uint32_t m, uint32_t bytes) {
    asm volatile("mbarrier.arrive.expect_tx.shared.b64 _, [%0], %1;"
                 :: "r"(m), "r"(bytes) : "memory");
}
__device__ __forceinline__ void bulk_ld(uint32_t dst, const void* src,
                                        uint32_t bytes, uint32_t m) {
    asm volatile("cp.async.bulk.shared::cluster.global.mbarrier::complete_tx::bytes "
                 "[%0], [%1], %2, [%3];"
                 :: "r"(dst), "l"(src), "r"(bytes), "r"(m) : "memory");
}
__device__ __forceinline__ void mbar_wait(uint32_t m, uint32_t phase) {
    uint32_t done;
    asm volatile("{\n\t.reg .pred p;\n\t"
                 "mbarrier.try_wait.parity.acquire.cta.shared::cta.b64 p, [%1], %2;\n\t"
                 "selp.b32 %0, 1, 0, p;\n\t}"
                 : "=r"(done) : "r"(m), "r"(phase) : "memory");
    if (!done) {
        asm volatile("{\n\t.reg .pred P1;\n\t"
                     "W_%=:\n\t"
                     "mbarrier.try_wait.parity.acquire.cta.shared::cta.b64 P1, [%0], %1, 0x989680;\n\t"
                     "@P1 bra.uni D_%=;\n\t"
                     "bra.uni W_%=;\n\t"
                     "D_%=:\n\t}" :: "r"(m), "r"(phase) : "memory");
    }
}

__global__ void __launch_bounds__(NT, BPSM) k_fused(
        const float* __restrict__ x,
        const float* __restrict__ enc_w,
        const float* __restrict__ enc_b,
        const float* __restrict__ vp,
        const float* __restrict__ gamma,
        const float* __restrict__ beta,
        float* __restrict__ out,
        int B)
{
    // per-warp private 3-deep sample rings: 8*3*576 floats = 55296 B
    __shared__ __align__(128) float buf[WPB * DEPTH * 576];
    __shared__ __align__(8) uint64_t mbar[WPB * DEPTH];
    __shared__ float Us[2 * 256];     // U re|im (init only)
    __shared__ float pw[WPB][28];     // per-warp: pooled[16] + cs[8] + pad
    __shared__ float encs[68];        // enc_w(64) + enc_b(4)
    __shared__ float wacc[WPB][8];    // per-warp BN partials
    __shared__ float stat[8];

    const int tid = threadIdx.x;
    const int wid = tid >> 5;
    const int lid = tid & 31;
    const long gw = (long)blockIdx.x * WPB + wid;   // global warp id

    const uint32_t mybuf0 = smem_u32(&buf[wid * DEPTH * 576]);
    const uint32_t mymb0  = smem_u32(&mbar[wid * DEPTH]);

    // ---- stage encoder ----
    if (tid >= 32 && tid < 96)  encs[tid - 32] = enc_w[tid - 32];
    if (tid >= 96 && tid < 100) encs[64 + tid - 96] = enc_b[tid - 96];

    // ---- per-warp prologue: own mbarriers + DEPTH prefetches ----
    if (lid == 0) {
#pragma unroll
        for (int d = 0; d < DEPTH; d++) mbar_init(mymb0 + d * 8, 1);
        asm volatile("fence.proxy.async.shared::cta;" ::: "memory");
#pragma unroll
        for (int d = 0; d < DEPTH; d++) {
            long s = gw + (long)d * TW;
            if (s < B) {
                mbar_expect_tx(mymb0 + d * 8, 2304u);
                bulk_ld(mybuf0 + d * 2304u, x + s * 576, 2304u, mymb0 + d * 8);
            }
        }
    }

    // ---- warp 0: build fixed variational unitary U into smem ----
    if (tid < 16) {
        float re[16], im[16];
#pragma unroll
        for (int b = 0; b < 16; b++) { re[b] = (b == tid) ? 1.f : 0.f; im[b] = 0.f; }
#pragma unroll
        for (int d = 0; d < 2; d++) {
#pragma unroll
            for (int w = 0; w < 4; w++) {
                const int mask = 8 >> w;
                float cx, sx, cy, sy, cz, sz;
                sincosf(0.5f * vp[d * 12 + w * 3 + 0], &sx, &cx);
                sincosf(0.5f * vp[d * 12 + w * 3 + 1], &sy, &cy);
                sincosf(0.5f * vp[d * 12 + w * 3 + 2], &sz, &cz);
#pragma unroll
                for (int b = 0; b < 16; b++) {
                    if (b & mask) continue;
                    const int b1 = b | mask;
                    float r0, i0, r1, i1;
                    r0 = re[b]; i0 = im[b]; r1 = re[b1]; i1 = im[b1];
                    re[b]  = cx * r0 + sx * i1;  im[b]  = cx * i0 - sx * r1;
                    re[b1] = cx * r1 + sx * i0;  im[b1] = cx * i1 - sx * r0;
                    r0 = re[b]; i0 = im[b]; r1 = re[b1]; i1 = im[b1];
                    re[b]  = cy * r0 - sy * r1;  im[b]  = cy * i0 - sy * i1;
                    re[b1] = sy * r0 + cy * r1;  im[b1] = sy * i0 + cy * i1;
                    r0 = re[b]; i0 = im[b]; r1 = re[b1]; i1 = im[b1];
                    re[b]  = cz * r0 + sz * i0;  im[b]  = cz * i0 - sz * r0;
                    re[b1] = cz * r1 - sz * i1;  im[b1] = cz * i1 + sz * r1;
                }
            }
#pragma unroll
            for (int c = 0; c < 4; c++) {
                const int tg = (c + 1) & 3;
                const int mc = 8 >> c, mt = 8 >> tg;
#pragma unroll
                for (int b = 0; b < 16; b++) {
                    if ((b & mc) && !(b & mt)) {
                        const int b1 = b | mt;
                        float tr = re[b], ti = im[b];
                        re[b] = re[b1]; im[b] = im[b1];
                        re[b1] = tr;    im[b1] = ti;
                    }
                }
            }
        }
#pragma unroll
        for (int b = 0; b < 16; b++) {
            Us[b * 16 + tid]       = re[b];
            Us[256 + b * 16 + tid] = im[b];
        }
    }
    __syncthreads();

    // ---- my U row into registers, sign-folded by (-i)^popc(col) ----
    const int cj = lid & 15;
    float fr[16], fi[16];
#pragma unroll
    for (int t = 0; t < 16; t++) {
        float urv = Us[cj * 16 + t], uiv = Us[256 + cj * 16 + t];
        const int k4 = __popc(t) & 3;
        if (k4 == 0)      { fr[t] = urv;  fi[t] = uiv;  }
        else if (k4 == 1) { fr[t] = uiv;  fi[t] = -urv; }
        else if (k4 == 2) { fr[t] = -urv; fi[t] = -uiv; }
        else              { fr[t] = -uiv; fi[t] = urv;  }
    }

    // ---- conflict-free pooling lane decomposition ----
    // lane = 8*wy + 4*h + wx ; reads float2 f = 72wy + 36h + 12dy + 3wx + i
    const int pwy = lid >> 3;
    const int phh = (lid >> 2) & 1;
    const int pwx = lid & 3;
    const int f0  = 72 * pwy + 36 * phh + 3 * pwx;

    float accS0 = 0.f, accS1 = 0.f, accS2 = 0.f, accS3 = 0.f;
    float accQ0 = 0.f, accQ1 = 0.f, accQ2 = 0.f, accQ3 = 0.f;

    // ============ per-warp autonomous sample loop (no block syncs) ============
    int it = 0;
    for (long samp = gw; samp < B; samp += TW, it++) {
        const int stage = it % DEPTH;
        const uint32_t mb = mymb0 + stage * 8;

        mbar_wait(mb, (it / DEPTH) & 1);

        // ---- pooling: 9 conflict-free LDS.64 per lane ----
        {
            const float2* p = (const float2*)(&buf[(wid * DEPTH + stage) * 576]) + f0;
            float s = 0.f;
#pragma unroll
            for (int dy = 0; dy < 3; dy++) {
                float2 a = p[dy * 12 + 0];
                float2 b = p[dy * 12 + 1];
                float2 c = p[dy * 12 + 2];
                s += a.x + a.y + b.x + b.y + c.x + c.y;
            }
            s += __shfl_down_sync(0xffffffffu, s, 4);   // combine halves
            if (phh == 0)
                pw[wid][pwy * 4 + pwx] = s * (1.f / 36.f);
        }
        __syncwarp();

        // ---- refill this slot for samp + DEPTH*TW (overlaps compute) ----
        if (lid == 0) {
            long sn = samp + (long)DEPTH * TW;
            if (sn < B) {
                mbar_expect_tx(mb, 2304u);
                bulk_ld(mybuf0 + stage * 2304u, x + sn * 576, 2304u, mb);
            }
        }

        // ---- angles + sincos: lanes 0..3 ----
        if (lid < 4) {
            float a = encs[64 + lid];
#pragma unroll
            for (int kk = 0; kk < 16; kk++)
                a = fmaf(encs[lid * 16 + kk], pw[wid][kk], a);
            float sv, cv;
            __sincosf(0.5f * a, &sv, &cv);
            pw[wid][16 + lid] = cv;
            pw[wid][20 + lid] = sv;
        }
        __syncwarp();

        // ---- circuit: U row in registers ----
        float z0, z1, z2, z3;
        {
            float c0 = pw[wid][16], c1 = pw[wid][17], c2 = pw[wid][18], c3 = pw[wid][19];
            float s0 = pw[wid][20], s1 = pw[wid][21], s2 = pw[wid][22], s3 = pw[wid][23];
            float p01[4], p23[4];
            p01[0] = c0 * c1; p01[1] = c0 * s1; p01[2] = s0 * c1; p01[3] = s0 * s1;
            p23[0] = c2 * c3; p23[1] = c2 * s3; p23[2] = s2 * c3; p23[3] = s2 * s3;
            float ar = 0.f, ai = 0.f;
#pragma unroll
            for (int t = 0; t < 16; t++) {
                float v = p01[t >> 2] * p23[t & 3];
                ar = fmaf(fr[t], v, ar);
                ai = fmaf(fi[t], v, ai);
            }
            float p = ar * ar + ai * ai;
            z0 = (cj & 8) ? -p : p;
            z1 = (cj & 4) ? -p : p;
            z2 = (cj & 2) ? -p : p;
            z3 = (cj & 1) ? -p : p;
        }
#pragma unroll
        for (int off = 8; off >= 1; off >>= 1) {
            z0 += __shfl_down_sync(0xffffffffu, z0, off, 16);
            z1 += __shfl_down_sync(0xffffffffu, z1, off, 16);
            z2 += __shfl_down_sync(0xffffffffu, z2, off, 16);
            z3 += __shfl_down_sync(0xffffffffu, z3, off, 16);
        }
        if (lid == 0) {
            ((float4*)g_zbuf)[samp] = make_float4(z0, z1, z2, z3);
            accS0 += z0; accS1 += z1; accS2 += z2; accS3 += z3;
            accQ0 += z0 * z0; accQ1 += z1 * z1; accQ2 += z2 * z2; accQ3 += z3 * z3;
        }
        __syncwarp();   // protect pw before next iteration's pooling writes
    }

    // ---- gather per-warp BN partials (deterministic) ----
    if (lid == 0) {
        wacc[wid][0] = accS0; wacc[wid][1] = accS1;
        wacc[wid][2] = accS2; wacc[wid][3] = accS3;
        wacc[wid][4] = accQ0; wacc[wid][5] = accQ1;
        wacc[wid][6] = accQ2; wacc[wid][7] = accQ3;
    }
    __syncthreads();
    if (tid < 4) {
        float S = 0.f, Q = 0.f;
#pragma unroll
        for (int w = 0; w < WPB; w++) {
            S += wacc[w][tid];
            Q += wacc[w][4 + tid];
        }
        g_part[blockIdx.x * 8 + tid]     = S;
        g_part[blockIdx.x * 8 + 4 + tid] = Q;
    }
    __threadfence();
    __syncthreads();
    if (tid == 0) {
        unsigned arr = atomicAdd(&g_bar, 1u) + 1u;
        unsigned target = ((arr + GRID - 1u) / GRID) * GRID;  // this launch's release
        while (*((volatile unsigned*)&g_bar) < target) {}
        __threadfence();
    }
    __syncthreads();

    // ---- redundant-but-deterministic stats reduction (each block) ----
    {
        float* red = &buf[0];   // reuse smem
        const int w = tid & 7, rr = tid >> 3;
        float S = 0.f;
        for (int i = rr; i < GRID; i += 32) S += g_part[i * 8 + w];
        red[tid] = S;
        __syncthreads();
#pragma unroll
        for (int step = 128; step >= 8; step >>= 1) {
            if (tid < step) red[tid] += red[tid + step];
            __syncthreads();
        }
        if (tid < 4) {
            float mean = red[tid] / (float)B;
            float var  = red[4 + tid] / (float)B - mean * mean;
            float sc   = gamma[tid] * rsqrtf(var + BN_EPS);
            stat[tid]     = sc;
            stat[4 + tid] = beta[tid] - mean * sc;
        }
        __syncthreads();
    }

    // ---- normalize (z is L2-resident) ----
    const float n0 = stat[0], n1 = stat[1], n2 = stat[2], n3 = stat[3];
    const float h0 = stat[4], h1 = stat[5], h2 = stat[6], h3 = stat[7];
    for (int b = blockIdx.x * NT + tid; b < B; b += GRID * NT) {
        float4 z = ((const float4*)g_zbuf)[b];
        ((float4*)out)[b] = make_float4(fmaf(z.x, n0, h0), fmaf(z.y, n1, h1),
                                        fmaf(z.z, n2, h2), fmaf(z.w, n3, h3));
    }
}

extern "C" void kernel_launch(void* const* d_in, const int* in_sizes, int n_in,
                              void* d_out, int out_size)
{
    const float* x      = (const float*)d_in[0];
    const float* enc_w  = (const float*)d_in[1];
    const float* enc_b  = (const float*)d_in[2];
    const float* vp     = (const float*)d_in[3];
    const float* gamma  = (const float*)d_in[4];
    const float* beta   = (const float*)d_in[5];

    const int B = in_sizes[0] / 576;   // [B,1,24,24]

    k_fused<<<GRID, NT>>>(x, enc_w, enc_b, vp, gamma, beta, (float*)d_out, B);
}

// round 10
// speedup vs baseline: 1.4114x; 1.0903x over previous
#include <cuda_runtime.h>
#include <math.h>
#include <stdint.h>

#define BN_EPS 1e-5f
#define WPB 8                  /* warps per block */
#define NT 256
#define DEPTH 2                /* per-warp ring depth (pairs) */
#define BPSM 2
#define NSM 148
#define GRID (NSM * BPSM)      /* 296 blocks, guaranteed co-resident */
#define TWP (GRID * WPB)       /* 2368 warps = pair stride */
#define MAXB 65536
#define PAIR_FLOATS 1152       /* 2 samples */
#define PAIR_BYTES  4608

// persistent scratch (no allocation allowed)
__device__ float g_zbuf[MAXB * 4];
__device__ float g_part[GRID * 8];
__device__ unsigned g_bar;     // monotone arrival counter (never reset)

__device__ __forceinline__ uint32_t smem_u32(const void* p) {
    uint32_t a;
    asm("{ .reg .u64 t; cvta.to.shared.u64 t, %1; cvt.u32.u64 %0, t; }"
        : "=r"(a) : "l"(p));
    return a;
}
__device__ __forceinline__ void mbar_init(uint32_t m, uint32_t cnt) {
    asm volatile("mbarrier.init.shared.b64 [%0], %1;" :: "r"(m), "r"(cnt) : "memory");
}
__device__ __forceinline__ void mbar_expect_tx(uint32_t m, uint32_t bytes) {
    asm volatile("mbarrier.arrive.expect_tx.shared.b64 _, [%0], %1;"
                 :: "r"(m), "r"(bytes) : "memory");
}
__device__ __forceinline__ void bulk_ld(uint32_t dst, const void* src,
                                        uint32_t bytes, uint32_t m) {
    asm volatile("cp.async.bulk.shared::cluster.global.mbarrier::complete_tx::bytes "
                 "[%0], [%1], %2, [%3];"
                 :: "r"(dst), "l"(src), "r"(bytes), "r"(m) : "memory");
}
__device__ __forceinline__ void mbar_wait(uint32_t m, uint32_t phase) {
    uint32_t done;
    asm volatile("{\n\t.reg .pred p;\n\t"
                 "mbarrier.try_wait.parity.acquire.cta.shared::cta.b64 p, [%1], %2;\n\t"
                 "selp.b32 %0, 1, 0, p;\n\t}"
                 : "=r"(done) : "r"(m), "r"(phase) : "memory");
    if (!done) {
        asm volatile("{\n\t.reg .pred P1;\n\t"
                     "W_%=:\n\t"
                     "mbarrier.try_wait.parity.acquire.cta.shared::cta.b64 P1, [%0], %1, 0x989680;\n\t"
                     "@P1 bra.uni D_%=;\n\t"
                     "bra.uni W_%=;\n\t"
                     "D_%=:\n\t}" :: "r"(m), "r"(phase) : "memory");
    }
}

__global__ void __launch_bounds__(NT, BPSM) k_fused(
        const float* __restrict__ x,
        const float* __restrict__ enc_w,
        const float* __restrict__ enc_b,
        const float* __restrict__ vp,
        const float* __restrict__ gamma,
        const float* __restrict__ beta,
        float* __restrict__ out,
        int B)
{
    // per-warp private 2-deep pair rings: 8*2*1152 floats = 73728 B
    __shared__ __align__(128) float buf[WPB * DEPTH * PAIR_FLOATS];
    __shared__ __align__(8) uint64_t mbar[WPB * DEPTH];
    __shared__ float Us[2 * 256];     // U re|im (init only)
    __shared__ float pw[WPB][48];     // pooled A[16] B[16], cs A[8] B[8]
    __shared__ float encs[68];        // enc_w(64) + enc_b(4)
    __shared__ float wacc[WPB][8];    // per-warp BN partials
    __shared__ float stat[8];

    const int tid = threadIdx.x;
    const int wid = tid >> 5;
    const int lid = tid & 31;
    const long gwp = (long)blockIdx.x * WPB + wid;   // global pair-warp id

    const uint32_t mybuf0 = smem_u32(&buf[wid * DEPTH * PAIR_FLOATS]);
    const uint32_t mymb0  = smem_u32(&mbar[wid * DEPTH]);

    // ---- stage encoder ----
    if (tid >= 32 && tid < 96)  encs[tid - 32] = enc_w[tid - 32];
    if (tid >= 96 && tid < 100) encs[64 + tid - 96] = enc_b[tid - 96];

    // ---- per-warp prologue: own mbarriers + DEPTH pair prefetches ----
    if (lid == 0) {
#pragma unroll
        for (int d = 0; d < DEPTH; d++) mbar_init(mymb0 + d * 8, 1);
        asm volatile("fence.proxy.async.shared::cta;" ::: "memory");
#pragma unroll
        for (int d = 0; d < DEPTH; d++) {
            long p = gwp + (long)d * TWP;
            long s0 = 2 * p;
            if (s0 < B) {
                uint32_t bytes = (uint32_t)min(2L, B - s0) * 2304u;
                mbar_expect_tx(mymb0 + d * 8, bytes);
                bulk_ld(mybuf0 + d * PAIR_BYTES, x + s0 * 576, bytes, mymb0 + d * 8);
            }
        }
    }

    // ---- warp 0: build fixed variational unitary U into smem ----
    if (tid < 16) {
        float re[16], im[16];
#pragma unroll
        for (int b = 0; b < 16; b++) { re[b] = (b == tid) ? 1.f : 0.f; im[b] = 0.f; }
#pragma unroll
        for (int d = 0; d < 2; d++) {
#pragma unroll
            for (int w = 0; w < 4; w++) {
                const int mask = 8 >> w;
                float cx, sx, cy, sy, cz, sz;
                sincosf(0.5f * vp[d * 12 + w * 3 + 0], &sx, &cx);
                sincosf(0.5f * vp[d * 12 + w * 3 + 1], &sy, &cy);
                sincosf(0.5f * vp[d * 12 + w * 3 + 2], &sz, &cz);
#pragma unroll
                for (int b = 0; b < 16; b++) {
                    if (b & mask) continue;
                    const int b1 = b | mask;
                    float r0, i0, r1, i1;
                    r0 = re[b]; i0 = im[b]; r1 = re[b1]; i1 = im[b1];
                    re[b]  = cx * r0 + sx * i1;  im[b]  = cx * i0 - sx * r1;
                    re[b1] = cx * r1 + sx * i0;  im[b1] = cx * i1 - sx * r0;
                    r0 = re[b]; i0 = im[b]; r1 = re[b1]; i1 = im[b1];
                    re[b]  = cy * r0 - sy * r1;  im[b]  = cy * i0 - sy * i1;
                    re[b1] = sy * r0 + cy * r1;  im[b1] = sy * i0 + cy * i1;
                    r0 = re[b]; i0 = im[b]; r1 = re[b1]; i1 = im[b1];
                    re[b]  = cz * r0 + sz * i0;  im[b]  = cz * i0 - sz * r0;
                    re[b1] = cz * r1 - sz * i1;  im[b1] = cz * i1 + sz * r1;
                }
            }
#pragma unroll
            for (int c = 0; c < 4; c++) {
                const int tg = (c + 1) & 3;
                const int mc = 8 >> c, mt = 8 >> tg;
#pragma unroll
                for (int b = 0; b < 16; b++) {
                    if ((b & mc) && !(b & mt)) {
                        const int b1 = b | mt;
                        float tr = re[b], ti = im[b];
                        re[b] = re[b1]; im[b] = im[b1];
                        re[b1] = tr;    im[b1] = ti;
                    }
                }
            }
        }
#pragma unroll
        for (int b = 0; b < 16; b++) {
            Us[b * 16 + tid]       = re[b];
            Us[256 + b * 16 + tid] = im[b];
        }
    }
    __syncthreads();

    // ---- my U row into registers, sign-folded by (-i)^popc(col) ----
    const int cj = lid & 15;
    float fr[16], fi[16];
#pragma unroll
    for (int t = 0; t < 16; t++) {
        float urv = Us[cj * 16 + t], uiv = Us[256 + cj * 16 + t];
        const int k4 = __popc(t) & 3;
        if (k4 == 0)      { fr[t] = urv;  fi[t] = uiv;  }
        else if (k4 == 1) { fr[t] = uiv;  fi[t] = -urv; }
        else if (k4 == 2) { fr[t] = -urv; fi[t] = -uiv; }
        else              { fr[t] = -uiv; fi[t] = urv;  }
    }

    // ---- conflict-free pooling lane decomposition ----
    const int pwy = lid >> 3;
    const int phh = (lid >> 2) & 1;
    const int pwx = lid & 3;
    const int f0  = 72 * pwy + 36 * phh + 3 * pwx;   // float2 units
    const int half = lid >> 4;                        // circuit: 0=A, 1=B

    float accS0 = 0.f, accS1 = 0.f, accS2 = 0.f, accS3 = 0.f;
    float accQ0 = 0.f, accQ1 = 0.f, accQ2 = 0.f, accQ3 = 0.f;

    // ============ per-warp pair loop (no block syncs) ============
    int it = 0;
    for (long pr = gwp; 2 * pr < B; pr += TWP, it++) {
        const int stage = it % DEPTH;
        const uint32_t mb = mymb0 + stage * 8;
        const long samp0 = 2 * pr;

        mbar_wait(mb, (it / DEPTH) & 1);

        // ---- pooling: conflict-free, run for both samples ----
        {
            const float2* p = (const float2*)(&buf[(wid * DEPTH + stage) * PAIR_FLOATS]) + f0;
#pragma unroll
            for (int smp = 0; smp < 2; smp++) {
                const float2* q = p + smp * 288;
                float s = 0.f;
#pragma unroll
                for (int dy = 0; dy < 3; dy++) {
                    float2 a = q[dy * 12 + 0];
                    float2 b = q[dy * 12 + 1];
                    float2 c = q[dy * 12 + 2];
                    s += a.x + a.y + b.x + b.y + c.x + c.y;
                }
                s += __shfl_down_sync(0xffffffffu, s, 4);
                if (phh == 0)
                    pw[wid][smp * 16 + pwy * 4 + pwx] = s * (1.f / 36.f);
            }
        }
        __syncwarp();

        // ---- refill this slot for pair + DEPTH*TWP (overlaps compute) ----
        if (lid == 0) {
            long pn = pr + (long)DEPTH * TWP;
            long sn = 2 * pn;
            if (sn < B) {
                uint32_t bytes = (uint32_t)min(2L, B - sn) * 2304u;
                mbar_expect_tx(mb, bytes);
                bulk_ld(mybuf0 + stage * PAIR_BYTES, x + sn * 576, bytes, mb);
            }
        }

        // ---- angles + sincos: lanes 0..7 (4 per sample) ----
        if (lid < 8) {
            const int smp = lid >> 2, i = lid & 3;
            float a = encs[64 + i];
#pragma unroll
            for (int kk = 0; kk < 16; kk++)
                a = fmaf(encs[i * 16 + kk], pw[wid][smp * 16 + kk], a);
            float sv, cv;
            __sincosf(0.5f * a, &sv, &cv);
            pw[wid][32 + smp * 8 + i] = cv;
            pw[wid][32 + smp * 8 + 4 + i] = sv;
        }
        __syncwarp();

        // ---- circuit: lanes 0-15 sample A, lanes 16-31 sample B ----
        float z0, z1, z2, z3;
        {
            const float* c = &pw[wid][32 + half * 8];
            float c0 = c[0], c1 = c[1], c2 = c[2], c3 = c[3];
            float s0 = c[4], s1 = c[5], s2 = c[6], s3 = c[7];
            float p01[4], p23[4];
            p01[0] = c0 * c1; p01[1] = c0 * s1; p01[2] = s0 * c1; p01[3] = s0 * s1;
            p23[0] = c2 * c3; p23[1] = c2 * s3; p23[2] = s2 * c3; p23[3] = s2 * s3;
            float ar = 0.f, ai = 0.f;
#pragma unroll
            for (int t = 0; t < 16; t++) {
                float v = p01[t >> 2] * p23[t & 3];
                ar = fmaf(fr[t], v, ar);
                ai = fmaf(fi[t], v, ai);
            }
            float p = ar * ar + ai * ai;
            z0 = (cj & 8) ? -p : p;
            z1 = (cj & 4) ? -p : p;
            z2 = (cj & 2) ? -p : p;
            z3 = (cj & 1) ? -p : p;
        }
#pragma unroll
        for (int off = 8; off >= 1; off >>= 1) {
            z0 += __shfl_down_sync(0xffffffffu, z0, off, 16);
            z1 += __shfl_down_sync(0xffffffffu, z1, off, 16);
            z2 += __shfl_down_sync(0xffffffffu, z2, off, 16);
            z3 += __shfl_down_sync(0xffffffffu, z3, off, 16);
        }
        if (cj == 0 && samp0 + half < B) {
            ((float4*)g_zbuf)[samp0 + half] = make_float4(z0, z1, z2, z3);
            accS0 += z0; accS1 += z1; accS2 += z2; accS3 += z3;
            accQ0 += z0 * z0; accQ1 += z1 * z1; accQ2 += z2 * z2; accQ3 += z3 * z3;
        }
        __syncwarp();   // protect pw before next iteration's pooling writes
    }

    // ---- merge lane16 accumulators into lane0 (deterministic) ----
    accS0 += __shfl_down_sync(0xffffffffu, accS0, 16);
    accS1 += __shfl_down_sync(0xffffffffu, accS1, 16);
    accS2 += __shfl_down_sync(0xffffffffu, accS2, 16);
    accS3 += __shfl_down_sync(0xffffffffu, accS3, 16);
    accQ0 += __shfl_down_sync(0xffffffffu, accQ0, 16);
    accQ1 += __shfl_down_sync(0xffffffffu, accQ1, 16);
    accQ2 += __shfl_down_sync(0xffffffffu, accQ2, 16);
    accQ3 += __shfl_down_sync(0xffffffffu, accQ3, 16);
    if (lid == 0) {
        wacc[wid][0] = accS0; wacc[wid][1] = accS1;
        wacc[wid][2] = accS2; wacc[wid][3] = accS3;
        wacc[wid][4] = accQ0; wacc[wid][5] = accQ1;
        wacc[wid][6] = accQ2; wacc[wid][7] = accQ3;
    }
    __syncthreads();
    if (tid < 4) {
        float S = 0.f, Q = 0.f;
#pragma unroll
        for (int w = 0; w < WPB; w++) {
            S += wacc[w][tid];
            Q += wacc[w][4 + tid];
        }
        g_part[blockIdx.x * 8 + tid]     = S;
        g_part[blockIdx.x * 8 + 4 + tid] = Q;
    }
    __threadfence();
    __syncthreads();
    if (tid == 0) {
        unsigned arr = atomicAdd(&g_bar, 1u) + 1u;
        unsigned target = ((arr + GRID - 1u) / GRID) * GRID;  // this launch's release
        while (*((volatile unsigned*)&g_bar) < target) {}
        __threadfence();
    }
    __syncthreads();

    // ---- redundant-but-deterministic stats reduction (each block) ----
    {
        float* red = &buf[0];   // reuse smem
        const int w = tid & 7, rr = tid >> 3;
        float S = 0.f;
        for (int i = rr; i < GRID; i += 32) S += g_part[i * 8 + w];
        red[tid] = S;
        __syncthreads();
#pragma unroll
        for (int step = 128; step >= 8; step >>= 1) {
            if (tid < step) red[tid] += red[tid + step];
            __syncthreads();
        }
        if (tid < 4) {
            float mean = red[tid] / (float)B;
            float var  = red[4 + tid] / (float)B - mean * mean;
            float sc   = gamma[tid] * rsqrtf(var + BN_EPS);
            stat[tid]     = sc;
            stat[4 + tid] = beta[tid] - mean * sc;
        }
        __syncthreads();
    }

    // ---- normalize (z is L2-resident) ----
    const float n0 = stat[0], n1 = stat[1], n2 = stat[2], n3 = stat[3];
    const float h0 = stat[4], h1 = stat[5], h2 = stat[6], h3 = stat[7];
    for (int b = blockIdx.x * NT + tid; b < B; b += GRID * NT) {
        float4 z = ((const float4*)g_zbuf)[b];
        ((float4*)out)[b] = make_float4(fmaf(z.x, n0, h0), fmaf(z.y, n1, h1),
                                        fmaf(z.z, n2, h2), fmaf(z.w, n3, h3));
    }
}

extern "C" void kernel_launch(void* const* d_in, const int* in_sizes, int n_in,
                              void* d_out, int out_size)
{
    const float* x      = (const float*)d_in[0];
    const float* enc_w  = (const float*)d_in[1];
    const float* enc_b  = (const float*)d_in[2];
    const float* vp     = (const float*)d_in[3];
    const float* gamma  = (const float*)d_in[4];
    const float* beta   = (const float*)d_in[5];

    const int B = in_sizes[0] / 576;   // [B,1,24,24]

    k_fused<<<GRID, NT>>>(x, enc_w, enc_b, vp, gamma, beta, (float*)d_out, B);
}